// round 11
// baseline (speedup 1.0000x reference)
#include <cuda_runtime.h>
#include <cuda_bf16.h>
#include <cuda_fp16.h>
#include <cstdint>
#include <cstddef>

#define N_NODES 100000
#define N_EDGES 1600000
#define IN_DIM  256
#define OUT_DIM 128

// ---------------- scratch (no cudaMalloc allowed) ----------------
__device__ __half g_h16[(size_t)N_NODES * OUT_DIM]; // h (unscaled, fp16)  (25.6 MB)
__device__ uint32_t g_wcb[32768];                   // Wc as tf32 bits, [ch][n][kloc]
__device__ float g_dinv[N_NODES];                   // 1/sqrt(deg)
__device__ int   g_cnt[N_NODES];                    // in-degree (edges only)
__device__ int   g_cur[N_NODES];                    // scatter cursors
__device__ int   g_rowptr[N_NODES + 1];             // CSR row pointers (by target)
__device__ int   g_srcs[N_EDGES];                   // sorted-by-target source ids
__device__ int   g_incl[N_NODES];                   // per-chunk inclusive scans
__device__ int   g_bsum[512];                       // block sums for scan
__device__ int   g_is64;                            // edge_index dtype flag

__device__ __forceinline__ uint32_t f32_to_tf32(float f) {
    uint32_t u;
    asm("cvt.rna.tf32.f32 %0, %1;" : "=r"(u) : "f"(f));
    return u;
}

__device__ __forceinline__ uint32_t smem_u32(const void* p) {
    uint32_t a;
    asm("{ .reg .u64 t; cvta.to.shared.u64 t, %1; cvt.u32.u64 %0, t; }" : "=r"(a) : "l"(p));
    return a;
}

__device__ __forceinline__ void cp16(uint32_t dst, const void* src, bool pred) {
    int sz = pred ? 16 : 0;
    asm volatile("cp.async.ca.shared.global [%0], [%1], 16, %2;"
                 :: "r"(dst), "l"(src), "r"(sz) : "memory");
}

// ---------------- dtype detection (int64 vs int32 edge_index) ----------------
__global__ void detect_kernel(const void* __restrict__ ei) {
    if (threadIdx.x == 0 && blockIdx.x == 0) {
        const long long* p = (const long long*)ei;
        int is64 = 1;
        for (int i = 0; i < 8; i++) {
            long long v = p[i];
            if (v < 0 || v >= N_NODES) { is64 = 0; break; }
        }
        g_is64 = is64;
    }
}

// ---------------- Wc = Wg @ Wp, converted to tf32 bits ----------------
// layout (u32): [ch][n][kloc]  ch = k>>5, kloc = k&31
__global__ void wc_kernel(const float* __restrict__ Wp, const float* __restrict__ Wg) {
    __shared__ float sWg[OUT_DIM];
    const int o2 = blockIdx.x;     // 0..127 (output row n)
    const int i  = threadIdx.x;    // 0..255 (k)
    if (i < OUT_DIM) sWg[i] = Wg[o2 * OUT_DIM + i];
    __syncthreads();
    float acc = 0.f;
#pragma unroll 8
    for (int o = 0; o < OUT_DIM; o++)
        acc += sWg[o] * Wp[o * IN_DIM + i];
    g_wcb[(i >> 5) * 4096 + o2 * 32 + (i & 31)] = f32_to_tf32(acc);
}

// ---------------- CSR build ----------------
__global__ void zero_cnt_kernel(int nN) {
    int i = blockIdx.x * blockDim.x + threadIdx.x;
    if (i < nN) g_cnt[i] = 0;
}

// 2 edges per thread, vectorized index loads
__global__ void hist_kernel(const void* __restrict__ ei, int nE) {
    int t = blockIdx.x * blockDim.x + threadIdx.x;
    int e = t * 2;
    if (e >= nE) return;
    int is64 = g_is64;
    int c0, c1 = -1;
    if (is64) {
        longlong2 v = __ldg((const longlong2*)((const long long*)ei + nE) + t);
        c0 = (int)v.x;
        if (e + 1 < nE) c1 = (int)v.y;
    } else {
        int2 v = __ldg((const int2*)((const int*)ei + nE) + t);
        c0 = v.x;
        if (e + 1 < nE) c1 = v.y;
    }
    atomicAdd(&g_cnt[c0], 1);
    if (c1 >= 0) atomicAdd(&g_cnt[c1], 1);
}

__global__ void scanA_kernel(int nN) {
    __shared__ int s[256];
    int tid = threadIdx.x;
    int i = blockIdx.x * 256 + tid;
    int v = (i < nN) ? g_cnt[i] : 0;
    s[tid] = v;
    __syncthreads();
#pragma unroll
    for (int o = 1; o < 256; o <<= 1) {
        int t = (tid >= o) ? s[tid - o] : 0;
        __syncthreads();
        s[tid] += t;
        __syncthreads();
    }
    if (i < nN) g_incl[i] = s[tid];
    if (tid == 255) g_bsum[blockIdx.x] = s[255];
}

__global__ void scanB_kernel(int nb) {
    __shared__ int s[512];
    int tid = threadIdx.x;
    int v = (tid < nb) ? g_bsum[tid] : 0;
    s[tid] = v;
    __syncthreads();
#pragma unroll
    for (int o = 1; o < 512; o <<= 1) {
        int t = (tid >= o) ? s[tid - o] : 0;
        __syncthreads();
        s[tid] += t;
        __syncthreads();
    }
    if (tid < nb) g_bsum[tid] = s[tid] - v;   // exclusive
}

__global__ void scanC_kernel(int nN, int nE) {
    int i = blockIdx.x * blockDim.x + threadIdx.x;
    if (i >= nN) return;
    int incl = g_incl[i] + g_bsum[i >> 8];
    g_rowptr[i + 1] = incl;
    int cnt = g_cnt[i];
    g_cur[i] = incl - cnt;                    // exclusive offset
    g_dinv[i] = rsqrtf((float)(cnt + 1));     // +1 for self loop
    if (i == 0) g_rowptr[0] = 0;
}

// 2 edges per thread, vectorized index loads
__global__ void permute_kernel(const void* __restrict__ ei, int nE) {
    int t = blockIdx.x * blockDim.x + threadIdx.x;
    int e = t * 2;
    if (e >= nE) return;
    int is64 = g_is64;
    int r0, c0, r1 = -1, c1 = -1;
    if (is64) {
        longlong2 rv = __ldg((const longlong2*)((const long long*)ei) + t);
        longlong2 cv = __ldg((const longlong2*)((const long long*)ei + nE) + t);
        r0 = (int)rv.x; c0 = (int)cv.x;
        if (e + 1 < nE) { r1 = (int)rv.y; c1 = (int)cv.y; }
    } else {
        int2 rv = __ldg((const int2*)((const int*)ei) + t);
        int2 cv = __ldg((const int2*)((const int*)ei + nE) + t);
        r0 = rv.x; c0 = cv.x;
        if (e + 1 < nE) { r1 = rv.y; c1 = cv.y; }
    }
    int p0 = atomicAdd(&g_cur[c0], 1);
    g_srcs[p0] = r0;
    if (r1 >= 0) {
        int p1 = atomicAdd(&g_cur[c1], 1);
        g_srcs[p1] = r1;
    }
}

// ---------------- GEMM via mma.sync tf32 + cp.async pipeline -------------------
// CTA tile 128(M) x 128(N), K=256 in 8 chunks of 32. 8 warps = 4(M) x 2(N).
// Double-buffered dynamic smem: A raw fp32 (cvt at fragment load), B tf32 bits.
#define KC 32
#define NCHUNK (IN_DIM / KC)
#define SROWA 36   // u32 per smem row: 32 data + 4 pad (144B stride)
#define ABUF_U32 (128 * SROWA)          // 4608
#define GEMM_SMEM_BYTES (4 * ABUF_U32 * 4)  // A0,A1,B0,B1 = 73728 B

__device__ __forceinline__ void mma_tf32(float* c, const uint32_t* a, uint32_t b0, uint32_t b1) {
    asm volatile(
        "mma.sync.aligned.m16n8k8.row.col.f32.tf32.tf32.f32 "
        "{%0,%1,%2,%3}, {%4,%5,%6,%7}, {%8,%9}, {%0,%1,%2,%3};"
        : "+f"(c[0]), "+f"(c[1]), "+f"(c[2]), "+f"(c[3])
        : "r"(a[0]), "r"(a[1]), "r"(a[2]), "r"(a[3]), "r"(b0), "r"(b1));
}

__device__ __forceinline__ void stage_chunk(uint32_t sbase, int buf, const float* __restrict__ x,
                                            int m0, int ch, int tid, int nN) {
    const int kk = ch * KC;
#pragma unroll
    for (int i = 0; i < 4; i++) {
        int idx = tid + i * 256;
        int row = idx >> 3, q = idx & 7;
        int gm  = m0 + row;
        uint32_t dA = sbase + (uint32_t)(buf * ABUF_U32 + row * SROWA + q * 4) * 4u;
        cp16(dA, x + (size_t)gm * IN_DIM + kk + q * 4, gm < nN);
    }
    const uint4* bsrc = (const uint4*)(g_wcb + ch * 4096);
#pragma unroll
    for (int i = 0; i < 4; i++) {
        int idx = tid + i * 256;
        int n = idx >> 3, q = idx & 7;
        uint32_t dB = sbase + (uint32_t)((2 + buf) * ABUF_U32 + n * SROWA + q * 4) * 4u;
        cp16(dB, bsrc + idx, true);
    }
}

__global__ void __launch_bounds__(256) gemm_mma_kernel(const float* __restrict__ x, int nN) {
    extern __shared__ uint32_t smemD[];
    uint32_t sbase = smem_u32(smemD);

    const int tid  = threadIdx.x;
    const int wid  = tid >> 5;
    const int lane = tid & 31;
    const int g    = lane >> 2;   // groupID
    const int tg   = lane & 3;    // thread in group
    const int wm   = wid >> 1;    // 0..3  -> m offset 32*wm
    const int wn   = wid & 1;     // 0..1  -> n offset 64*wn
    const int m0   = blockIdx.x * 128;

    float acc[2][8][4];
#pragma unroll
    for (int mt = 0; mt < 2; mt++)
#pragma unroll
        for (int nt = 0; nt < 8; nt++)
#pragma unroll
            for (int j = 0; j < 4; j++) acc[mt][nt][j] = 0.f;

    stage_chunk(sbase, 0, x, m0, 0, tid, nN);
    asm volatile("cp.async.commit_group;" ::: "memory");

    for (int ch = 0; ch < NCHUNK; ch++) {
        const int buf = ch & 1;
        if (ch + 1 < NCHUNK) {
            stage_chunk(sbase, buf ^ 1, x, m0, ch + 1, tid, nN);
            asm volatile("cp.async.commit_group;" ::: "memory");
            asm volatile("cp.async.wait_group 1;" ::: "memory");
        } else {
            asm volatile("cp.async.wait_group 0;" ::: "memory");
        }
        __syncthreads();

        const uint32_t* sa = smemD + buf * ABUF_U32;
        const uint32_t* sb = smemD + (2 + buf) * ABUF_U32;

#pragma unroll
        for (int ks = 0; ks < KC / 8; ks++) {
            const int kb = ks * 8;
            uint32_t a[2][4];
#pragma unroll
            for (int mt = 0; mt < 2; mt++) {
                int r0 = (wm * 32 + mt * 16 + g) * SROWA + kb + tg;
                int r1 = (wm * 32 + mt * 16 + g + 8) * SROWA + kb + tg;
                a[mt][0] = f32_to_tf32(__uint_as_float(sa[r0]));
                a[mt][1] = f32_to_tf32(__uint_as_float(sa[r1]));
                a[mt][2] = f32_to_tf32(__uint_as_float(sa[r0 + 4]));
                a[mt][3] = f32_to_tf32(__uint_as_float(sa[r1 + 4]));
            }
#pragma unroll
            for (int nt = 0; nt < 8; nt++) {
                int n = wn * 64 + nt * 8 + g;
                int o = n * SROWA + kb + tg;
                uint32_t b0 = sb[o], b1 = sb[o + 4];
#pragma unroll
                for (int mt = 0; mt < 2; mt++)
                    mma_tf32(acc[mt][nt], a[mt], b0, b1);
            }
        }
        __syncthreads();
    }

    // epilogue: store h (unscaled) as fp16
#pragma unroll
    for (int mt = 0; mt < 2; mt++) {
        int r0 = m0 + wm * 32 + mt * 16 + g;
        int r1 = r0 + 8;
#pragma unroll
        for (int nt = 0; nt < 8; nt++) {
            int col = wn * 64 + nt * 8 + tg * 2;
            if (r0 < nN) {
                __half2 o = __floats2half2_rn(acc[mt][nt][0], acc[mt][nt][1]);
                *(__half2*)(g_h16 + (size_t)r0 * OUT_DIM + col) = o;
            }
            if (r1 < nN) {
                __half2 o = __floats2half2_rn(acc[mt][nt][2], acc[mt][nt][3]);
                *(__half2*)(g_h16 + (size_t)r1 * OUT_DIM + col) = o;
            }
        }
    }
}

// ---------------- fused aggregate + finalize (paired-edge half-warp gather) ------
// Warp owns one node. Lanes 0-15 fetch even items, 16-31 odd items (uint4 = 8 fp16
// features per lane, 16 lanes per row). Item 0 = self loop, item j>0 = edge j-1.
__device__ __forceinline__ void accu4(float* a, uint4 raw, float d) {
    __half2* h = (__half2*)&raw;
#pragma unroll
    for (int k = 0; k < 4; k++) {
        float2 f = __half22float2(h[k]);
        a[2 * k]     += f.x * d;
        a[2 * k + 1] += f.y * d;
    }
}

__global__ void __launch_bounds__(256) aggregate_kernel(
    float* __restrict__ out, const float* __restrict__ bg, int nN) {
    int w    = (int)((blockIdx.x * (unsigned)blockDim.x + threadIdx.x) >> 5);
    int lane = threadIdx.x & 31;
    int hl   = lane >> 4;          // half id: item parity
    int sl   = lane & 15;          // sublane: feature group 8*sl..8*sl+7
    if (w >= nN) return;

    int beg = g_rowptr[w];
    int end = g_rowptr[w + 1];
    int nItems = 1 + (end - beg);  // self + edges
    float dw = g_dinv[w];

    float a[8] = {0.f, 0.f, 0.f, 0.f, 0.f, 0.f, 0.f, 0.f};

    int j = hl;
    // batched: 6 items per half per round (12 rows in flight warp-wide)
    for (; j + 10 < nItems; j += 12) {
        int rows[6];
#pragma unroll
        for (int t = 0; t < 6; t++) {
            int jj = j + 2 * t;
            rows[t] = (jj == 0) ? w : __ldg(&g_srcs[beg + jj - 1]);
        }
        uint4 rr[6];
#pragma unroll
        for (int t = 0; t < 6; t++)
            rr[t] = __ldg((const uint4*)(g_h16 + (size_t)rows[t] * OUT_DIM) + sl);
        float dd[6];
#pragma unroll
        for (int t = 0; t < 6; t++) dd[t] = __ldg(&g_dinv[rows[t]]);
#pragma unroll
        for (int t = 0; t < 6; t++) accu4(a, rr[t], dd[t]);
    }
    for (; j < nItems; j += 2) {
        int row = (j == 0) ? w : __ldg(&g_srcs[beg + j - 1]);
        uint4 r = __ldg((const uint4*)(g_h16 + (size_t)row * OUT_DIM) + sl);
        float d = __ldg(&g_dinv[row]);
        accu4(a, r, d);
    }

    // combine the two halves (same feature group in lanes sl and sl+16)
#pragma unroll
    for (int k = 0; k < 8; k++) a[k] += __shfl_xor_sync(0xffffffffu, a[k], 16);

    // bias + dinv scale
    float4 b0 = ((const float4*)bg)[sl * 2];
    float4 b1 = ((const float4*)bg)[sl * 2 + 1];
    a[0] = a[0] * dw + b0.x;  a[1] = a[1] * dw + b0.y;
    a[2] = a[2] * dw + b0.z;  a[3] = a[3] * dw + b0.w;
    a[4] = a[4] * dw + b1.x;  a[5] = a[5] * dw + b1.y;
    a[6] = a[6] * dw + b1.z;  a[7] = a[7] * dw + b1.w;

    float ss = 0.f;
#pragma unroll
    for (int k = 0; k < 8; k++) ss += a[k] * a[k];
#pragma unroll
    for (int o = 8; o > 0; o >>= 1) ss += __shfl_xor_sync(0xffffffffu, ss, o);
    float inv = 1.0f / fmaxf(sqrtf(ss), 1e-12f);

    // each lane stores one float4: half 0 -> features 8sl..+3, half 1 -> 8sl+4..+7
    float4 v = (hl == 0)
        ? make_float4(a[0] * inv, a[1] * inv, a[2] * inv, a[3] * inv)
        : make_float4(a[4] * inv, a[5] * inv, a[6] * inv, a[7] * inv);
    *(float4*)(out + (size_t)w * OUT_DIM + sl * 8 + hl * 4) = v;
}

// ---------------- launch (stream fork/join, capture-legal) ----------------
// Submission order puts gemm 4th so ncu (which profiles launch #4) shows it.
extern "C" void kernel_launch(void* const* d_in, const int* in_sizes, int n_in,
                              void* d_out, int out_size) {
    const float* x  = (const float*)d_in[0];
    const void*  ei = d_in[1];
    const float* Wp = (const float*)d_in[2];
    const float* Wg = (const float*)d_in[3];
    const float* bg = (const float*)d_in[4];
    float* out = (float*)d_out;

    const int nN = in_sizes[0] / IN_DIM;   // 100000
    const int nE = in_sizes[1] / 2;        // 1600000
    const int nScanBlocks = (nN + 255) / 256;
    const int nEdgeT = (nE + 1) / 2;       // 2 edges per thread

    static cudaStream_t s2;
    static cudaEvent_t evF, evJ;
    static bool inited = false;
    if (!inited) {
        cudaStreamCreateWithFlags(&s2, cudaStreamNonBlocking);
        cudaEventCreateWithFlags(&evF, cudaEventDisableTiming);
        cudaEventCreateWithFlags(&evJ, cudaEventDisableTiming);
        cudaFuncSetAttribute(gemm_mma_kernel,
                             cudaFuncAttributeMaxDynamicSharedMemorySize,
                             GEMM_SMEM_BYTES);
        inited = true;
    }

    // fork: CSR chain on s2, GEMM chain on default stream
    cudaEventRecord(evF, 0);
    cudaStreamWaitEvent(s2, evF, 0);

    detect_kernel<<<1, 32, 0, s2>>>(ei);                         // launch 1
    zero_cnt_kernel<<<(nN + 255) / 256, 256, 0, s2>>>(nN);       // launch 2
    wc_kernel<<<OUT_DIM, 256>>>(Wp, Wg);                         // launch 3
    gemm_mma_kernel<<<(nN + 127) / 128, 256, GEMM_SMEM_BYTES>>>(x, nN);  // launch 4
    hist_kernel<<<(nEdgeT + 255) / 256, 256, 0, s2>>>(ei, nE);
    scanA_kernel<<<nScanBlocks, 256, 0, s2>>>(nN);
    scanB_kernel<<<1, 512, 0, s2>>>(nScanBlocks);
    scanC_kernel<<<(nN + 255) / 256, 256, 0, s2>>>(nN, nE);
    permute_kernel<<<(nEdgeT + 255) / 256, 256, 0, s2>>>(ei, nE);
    cudaEventRecord(evJ, s2);

    // join
    cudaStreamWaitEvent(0, evJ, 0);

    long long agg_threads = (long long)nN * 32;
    int agg_blocks = (int)((agg_threads + 255) / 256);
    aggregate_kernel<<<agg_blocks, 256>>>(out, bg, nN);
}

// round 13
// speedup vs baseline: 1.2486x; 1.2486x over previous
#include <cuda_runtime.h>
#include <cuda_fp16.h>
#include <cstdint>
#include <cstddef>

#define N_NODES 100000
#define N_EDGES 1600000
#define IN_DIM  256
#define OUT_DIM 128

// ---------------- scratch (no cudaMalloc allowed) ----------------
__device__ __half g_h16[(size_t)N_NODES * OUT_DIM]; // h (unscaled, fp16)  (25.6 MB)
__device__ uint32_t g_wcf[16384];                   // Wc fp16 pairs, [ch][n][kloc]
__device__ float g_dinv[N_NODES];                   // 1/sqrt(deg)
__device__ int   g_cnt[N_NODES];                    // in-degree (edges only)
__device__ int   g_cur[N_NODES];                    // scatter cursors
__device__ int   g_rowptr[N_NODES + 1];             // CSR row pointers (by target)
__device__ int   g_srcs[N_EDGES];                   // sorted-by-target source ids
__device__ int   g_incl[N_NODES];                   // per-chunk inclusive scans
__device__ int   g_bsum[512];                       // block sums for scan
__device__ int   g_is64;                            // edge_index dtype flag

__device__ __forceinline__ uint32_t smem_u32(const void* p) {
    uint32_t a;
    asm("{ .reg .u64 t; cvta.to.shared.u64 t, %1; cvt.u32.u64 %0, t; }" : "=r"(a) : "l"(p));
    return a;
}

__device__ __forceinline__ uint32_t h2_bits(__half2 h) {
    uint32_t u;
    u = *reinterpret_cast<uint32_t*>(&h);
    return u;
}

__device__ __forceinline__ void cp16(uint32_t dst, const void* src) {
    asm volatile("cp.async.ca.shared.global [%0], [%1], 16;"
                 :: "r"(dst), "l"(src) : "memory");
}

// ---------------- dtype detection (int64 vs int32 edge_index) ----------------
__global__ void detect_kernel(const void* __restrict__ ei) {
    if (threadIdx.x == 0 && blockIdx.x == 0) {
        const long long* p = (const long long*)ei;
        int is64 = 1;
        for (int i = 0; i < 8; i++) {
            long long v = p[i];
            if (v < 0 || v >= N_NODES) { is64 = 0; break; }
        }
        g_is64 = is64;
    }
}

// ---------------- Wc = Wg @ Wp, converted to fp16 ----------------
// layout (half view): [ch][n][kloc]  ch = k>>5, kloc = k&31
__global__ void wc_kernel(const float* __restrict__ Wp, const float* __restrict__ Wg) {
    __shared__ float sWg[OUT_DIM];
    const int o2 = blockIdx.x;     // 0..127 (output row n)
    const int i  = threadIdx.x;    // 0..255 (k)
    if (i < OUT_DIM) sWg[i] = Wg[o2 * OUT_DIM + i];
    __syncthreads();
    float acc = 0.f;
#pragma unroll 8
    for (int o = 0; o < OUT_DIM; o++)
        acc += sWg[o] * Wp[o * IN_DIM + i];
    ((__half*)g_wcf)[(i >> 5) * 4096 + o2 * 32 + (i & 31)] = __float2half_rn(acc);
}

// ---------------- CSR build ----------------
__global__ void zero_cnt_kernel(int nN) {
    int i = blockIdx.x * blockDim.x + threadIdx.x;
    if (i < nN) g_cnt[i] = 0;
}

// 2 edges per thread, vectorized index loads
__global__ void hist_kernel(const void* __restrict__ ei, int nE) {
    int t = blockIdx.x * blockDim.x + threadIdx.x;
    int e = t * 2;
    if (e >= nE) return;
    int is64 = g_is64;
    int c0, c1 = -1;
    if (is64) {
        longlong2 v = __ldg((const longlong2*)((const long long*)ei + nE) + t);
        c0 = (int)v.x;
        if (e + 1 < nE) c1 = (int)v.y;
    } else {
        int2 v = __ldg((const int2*)((const int*)ei + nE) + t);
        c0 = v.x;
        if (e + 1 < nE) c1 = v.y;
    }
    atomicAdd(&g_cnt[c0], 1);
    if (c1 >= 0) atomicAdd(&g_cnt[c1], 1);
}

__global__ void scanA_kernel(int nN) {
    __shared__ int s[256];
    int tid = threadIdx.x;
    int i = blockIdx.x * 256 + tid;
    int v = (i < nN) ? g_cnt[i] : 0;
    s[tid] = v;
    __syncthreads();
#pragma unroll
    for (int o = 1; o < 256; o <<= 1) {
        int t = (tid >= o) ? s[tid - o] : 0;
        __syncthreads();
        s[tid] += t;
        __syncthreads();
    }
    if (i < nN) g_incl[i] = s[tid];
    if (tid == 255) g_bsum[blockIdx.x] = s[255];
}

__global__ void scanB_kernel(int nb) {
    __shared__ int s[512];
    int tid = threadIdx.x;
    int v = (tid < nb) ? g_bsum[tid] : 0;
    s[tid] = v;
    __syncthreads();
#pragma unroll
    for (int o = 1; o < 512; o <<= 1) {
        int t = (tid >= o) ? s[tid - o] : 0;
        __syncthreads();
        s[tid] += t;
        __syncthreads();
    }
    if (tid < nb) g_bsum[tid] = s[tid] - v;   // exclusive
}

__global__ void scanC_kernel(int nN, int nE) {
    int i = blockIdx.x * blockDim.x + threadIdx.x;
    if (i >= nN) return;
    int incl = g_incl[i] + g_bsum[i >> 8];
    g_rowptr[i + 1] = incl;
    int cnt = g_cnt[i];
    g_cur[i] = incl - cnt;                    // exclusive offset
    g_dinv[i] = rsqrtf((float)(cnt + 1));     // +1 for self loop
    if (i == 0) g_rowptr[0] = 0;
}

// 2 edges per thread, vectorized index loads
__global__ void permute_kernel(const void* __restrict__ ei, int nE) {
    int t = blockIdx.x * blockDim.x + threadIdx.x;
    int e = t * 2;
    if (e >= nE) return;
    int is64 = g_is64;
    int r0, c0, r1 = -1, c1 = -1;
    if (is64) {
        longlong2 rv = __ldg((const longlong2*)((const long long*)ei) + t);
        longlong2 cv = __ldg((const longlong2*)((const long long*)ei + nE) + t);
        r0 = (int)rv.x; c0 = (int)cv.x;
        if (e + 1 < nE) { r1 = (int)rv.y; c1 = (int)cv.y; }
    } else {
        int2 rv = __ldg((const int2*)((const int*)ei) + t);
        int2 cv = __ldg((const int2*)((const int*)ei + nE) + t);
        r0 = rv.x; c0 = cv.x;
        if (e + 1 < nE) { r1 = rv.y; c1 = cv.y; }
    }
    int p0 = atomicAdd(&g_cur[c0], 1);
    g_srcs[p0] = r0;
    if (r1 >= 0) {
        int p1 = atomicAdd(&g_cur[c1], 1);
        g_srcs[p1] = r1;
    }
}

// ---------------- GEMM via mma.sync fp16 single-pass: h = x @ Wc^T -------------
// CTA tile 128(M) x 128(N), K=256 in 8 chunks of 32. 8 warps = 4(M) x 2(N).
// Warp tile 32x64 = 2 m16-tiles x 8 n8-tiles, m16n8k16 per MMA.
// A: LDG f32 ping-pong regs -> cvt fp16 -> STS (single buffer).
// B: cp.async of pre-converted fp16 (double buffer).
#define KC 32
#define NCHUNK (IN_DIM / KC)
#define SROW 20   // u32 (fp16x2) per smem row: 16 data + 4 pad (80B stride)

__device__ __forceinline__ void mma_f16(float* c, const uint32_t* a, uint32_t b0, uint32_t b1) {
    asm volatile(
        "mma.sync.aligned.m16n8k16.row.col.f32.f16.f16.f32 "
        "{%0,%1,%2,%3}, {%4,%5,%6,%7}, {%8,%9}, {%0,%1,%2,%3};"
        : "+f"(c[0]), "+f"(c[1]), "+f"(c[2]), "+f"(c[3])
        : "r"(a[0]), "r"(a[1]), "r"(a[2]), "r"(a[3]), "r"(b0), "r"(b1));
}

__device__ __forceinline__ void loadA_regs(const float* __restrict__ x, int m0, int kk,
                                           int tid, int nN, float4* av) {
#pragma unroll
    for (int i = 0; i < 4; i++) {
        int idx = tid + i * 256;
        int row = idx >> 3, q = idx & 7;
        int gm  = m0 + row;
        av[i] = make_float4(0.f, 0.f, 0.f, 0.f);
        if (gm < nN) av[i] = __ldg((const float4*)(x + (size_t)gm * IN_DIM + kk + q * 4));
    }
}

__global__ void __launch_bounds__(256) gemm_mma_kernel(const float* __restrict__ x, int nN) {
    __shared__ __align__(16) uint32_t saF[128 * SROW];
    __shared__ __align__(16) uint32_t sbF[2][128 * SROW];

    const int tid  = threadIdx.x;
    const int wid  = tid >> 5;
    const int lane = tid & 31;
    const int g    = lane >> 2;   // groupID
    const int tg   = lane & 3;    // thread in group
    const int wm   = wid >> 1;    // 0..3  -> m offset 32*wm
    const int wn   = wid & 1;     // 0..1  -> n offset 64*wn
    const int m0   = blockIdx.x * 128;

    float acc[2][8][4];
#pragma unroll
    for (int mt = 0; mt < 2; mt++)
#pragma unroll
        for (int nt = 0; nt < 8; nt++)
#pragma unroll
            for (int j = 0; j < 4; j++) acc[mt][nt][j] = 0.f;

    float4 av[2][4];
    loadA_regs(x, m0, 0, tid, nN, av[0]);
    // stage B chunk 0 into buffer 0
    {
        const uint4* bsrc = (const uint4*)(g_wcf);
        uint32_t sb0 = smem_u32(&sbF[0][0]);
#pragma unroll
        for (int i = 0; i < 2; i++) {
            int idx = tid + i * 256;
            int n = idx >> 2, q = idx & 3;
            cp16(sb0 + (uint32_t)(n * SROW + q * 4) * 4u, bsrc + idx);
        }
        asm volatile("cp.async.commit_group;" ::: "memory");
    }

    for (int ch = 0; ch < NCHUNK; ch++) {
        const int buf = ch & 1;
        // STS A(ch) from regs (saF was released by previous iteration's trailing sync)
#pragma unroll
        for (int i = 0; i < 4; i++) {
            int idx = tid + i * 256;
            int row = idx >> 3, q = idx & 7;
            float4 v = av[buf][i];
            uint32_t p0 = h2_bits(__floats2half2_rn(v.x, v.y));
            uint32_t p1 = h2_bits(__floats2half2_rn(v.z, v.w));
            *(uint2*)&saF[row * SROW + q * 2] = make_uint2(p0, p1);
        }
        if (ch + 1 < NCHUNK) {
            // prefetch A(ch+1) into other reg set; stage B(ch+1)
            loadA_regs(x, m0, (ch + 1) * KC, tid, nN, av[buf ^ 1]);
            const uint4* bsrc = (const uint4*)(g_wcf + (ch + 1) * 2048);
            uint32_t sbn = smem_u32(&sbF[buf ^ 1][0]);
#pragma unroll
            for (int i = 0; i < 2; i++) {
                int idx = tid + i * 256;
                int n = idx >> 2, q = idx & 3;
                cp16(sbn + (uint32_t)(n * SROW + q * 4) * 4u, bsrc + idx);
            }
            asm volatile("cp.async.commit_group;" ::: "memory");
            asm volatile("cp.async.wait_group 1;" ::: "memory");
        } else {
            asm volatile("cp.async.wait_group 0;" ::: "memory");
        }
        __syncthreads();

        const uint32_t* sb = sbF[buf];
#pragma unroll
        for (int ks = 0; ks < KC / 16; ks++) {
            uint32_t a[2][4];
#pragma unroll
            for (int mt = 0; mt < 2; mt++) {
                int rbase = (wm * 32 + mt * 16) * SROW + ks * 8;
                a[mt][0] = saF[rbase + g * SROW + tg];
                a[mt][1] = saF[rbase + (g + 8) * SROW + tg];
                a[mt][2] = saF[rbase + g * SROW + tg + 4];
                a[mt][3] = saF[rbase + (g + 8) * SROW + tg + 4];
            }
#pragma unroll
            for (int nt = 0; nt < 8; nt++) {
                int n = wn * 64 + nt * 8 + g;
                int o = n * SROW + ks * 8 + tg;
                uint32_t b0 = sb[o], b1 = sb[o + 4];
#pragma unroll
                for (int mt = 0; mt < 2; mt++)
                    mma_f16(acc[mt][nt], a[mt], b0, b1);
            }
        }
        __syncthreads();
    }

    // epilogue: store h (unscaled) as fp16
#pragma unroll
    for (int mt = 0; mt < 2; mt++) {
        int r0 = m0 + wm * 32 + mt * 16 + g;
        int r1 = r0 + 8;
#pragma unroll
        for (int nt = 0; nt < 8; nt++) {
            int col = wn * 64 + nt * 8 + tg * 2;
            if (r0 < nN) {
                __half2 o = __floats2half2_rn(acc[mt][nt][0], acc[mt][nt][1]);
                *(__half2*)(g_h16 + (size_t)r0 * OUT_DIM + col) = o;
            }
            if (r1 < nN) {
                __half2 o = __floats2half2_rn(acc[mt][nt][2], acc[mt][nt][3]);
                *(__half2*)(g_h16 + (size_t)r1 * OUT_DIM + col) = o;
            }
        }
    }
}

// ---------------- fused aggregate + finalize (paired-edge half-warp gather) ------
__device__ __forceinline__ void accu4(float* a, uint4 raw, float d) {
    __half2* h = (__half2*)&raw;
#pragma unroll
    for (int k = 0; k < 4; k++) {
        float2 f = __half22float2(h[k]);
        a[2 * k]     += f.x * d;
        a[2 * k + 1] += f.y * d;
    }
}

__global__ void __launch_bounds__(256) aggregate_kernel(
    float* __restrict__ out, const float* __restrict__ bg, int nN) {
    int w    = (int)((blockIdx.x * (unsigned)blockDim.x + threadIdx.x) >> 5);
    int lane = threadIdx.x & 31;
    int hl   = lane >> 4;          // half id: item parity
    int sl   = lane & 15;          // sublane: feature group 8*sl..8*sl+7
    if (w >= nN) return;

    int beg = g_rowptr[w];
    int end = g_rowptr[w + 1];
    int nItems = 1 + (end - beg);  // self + edges
    float dw = g_dinv[w];

    float a[8] = {0.f, 0.f, 0.f, 0.f, 0.f, 0.f, 0.f, 0.f};

    int j = hl;
    for (; j + 10 < nItems; j += 12) {
        int rows[6];
#pragma unroll
        for (int t = 0; t < 6; t++) {
            int jj = j + 2 * t;
            rows[t] = (jj == 0) ? w : __ldg(&g_srcs[beg + jj - 1]);
        }
        uint4 rr[6];
#pragma unroll
        for (int t = 0; t < 6; t++)
            rr[t] = __ldg((const uint4*)(g_h16 + (size_t)rows[t] * OUT_DIM) + sl);
        float dd[6];
#pragma unroll
        for (int t = 0; t < 6; t++) dd[t] = __ldg(&g_dinv[rows[t]]);
#pragma unroll
        for (int t = 0; t < 6; t++) accu4(a, rr[t], dd[t]);
    }
    for (; j < nItems; j += 2) {
        int row = (j == 0) ? w : __ldg(&g_srcs[beg + j - 1]);
        uint4 r = __ldg((const uint4*)(g_h16 + (size_t)row * OUT_DIM) + sl);
        float d = __ldg(&g_dinv[row]);
        accu4(a, r, d);
    }

#pragma unroll
    for (int k = 0; k < 8; k++) a[k] += __shfl_xor_sync(0xffffffffu, a[k], 16);

    float4 b0 = ((const float4*)bg)[sl * 2];
    float4 b1 = ((const float4*)bg)[sl * 2 + 1];
    a[0] = a[0] * dw + b0.x;  a[1] = a[1] * dw + b0.y;
    a[2] = a[2] * dw + b0.z;  a[3] = a[3] * dw + b0.w;
    a[4] = a[4] * dw + b1.x;  a[5] = a[5] * dw + b1.y;
    a[6] = a[6] * dw + b1.z;  a[7] = a[7] * dw + b1.w;

    float ss = 0.f;
#pragma unroll
    for (int k = 0; k < 8; k++) ss += a[k] * a[k];
#pragma unroll
    for (int o = 8; o > 0; o >>= 1) ss += __shfl_xor_sync(0xffffffffu, ss, o);
    float inv = 1.0f / fmaxf(sqrtf(ss), 1e-12f);

    float4 v = (hl == 0)
        ? make_float4(a[0] * inv, a[1] * inv, a[2] * inv, a[3] * inv)
        : make_float4(a[4] * inv, a[5] * inv, a[6] * inv, a[7] * inv);
    *(float4*)(out + (size_t)w * OUT_DIM + sl * 8 + hl * 4) = v;
}

// ---------------- launch (stream fork/join, capture-legal) ----------------
// CSR chain submitted FIRST (round-10 order): small kernels grab SMs early and
// interleave with the GEMM; submitting the GEMM early serializes (round-11 lesson).
extern "C" void kernel_launch(void* const* d_in, const int* in_sizes, int n_in,
                              void* d_out, int out_size) {
    const float* x  = (const float*)d_in[0];
    const void*  ei = d_in[1];
    const float* Wp = (const float*)d_in[2];
    const float* Wg = (const float*)d_in[3];
    const float* bg = (const float*)d_in[4];
    float* out = (float*)d_out;

    const int nN = in_sizes[0] / IN_DIM;   // 100000
    const int nE = in_sizes[1] / 2;        // 1600000
    const int nScanBlocks = (nN + 255) / 256;
    const int nEdgeT = (nE + 1) / 2;       // 2 edges per thread

    static cudaStream_t s2;
    static cudaEvent_t evF, evJ;
    static bool inited = false;
    if (!inited) {
        cudaStreamCreateWithFlags(&s2, cudaStreamNonBlocking);
        cudaEventCreateWithFlags(&evF, cudaEventDisableTiming);
        cudaEventCreateWithFlags(&evJ, cudaEventDisableTiming);
        inited = true;
    }

    // fork: CSR chain on s2, GEMM chain on default stream
    cudaEventRecord(evF, 0);
    cudaStreamWaitEvent(s2, evF, 0);

    detect_kernel<<<1, 32, 0, s2>>>(ei);
    zero_cnt_kernel<<<(nN + 255) / 256, 256, 0, s2>>>(nN);
    hist_kernel<<<(nEdgeT + 255) / 256, 256, 0, s2>>>(ei, nE);
    scanA_kernel<<<nScanBlocks, 256, 0, s2>>>(nN);
    scanB_kernel<<<1, 512, 0, s2>>>(nScanBlocks);
    scanC_kernel<<<(nN + 255) / 256, 256, 0, s2>>>(nN, nE);
    permute_kernel<<<(nEdgeT + 255) / 256, 256, 0, s2>>>(ei, nE);
    cudaEventRecord(evJ, s2);

    wc_kernel<<<OUT_DIM, 256>>>(Wp, Wg);
    gemm_mma_kernel<<<(nN + 127) / 128, 256>>>(x, nN);

    // join
    cudaStreamWaitEvent(0, evJ, 0);

    long long agg_threads = (long long)nN * 32;
    int agg_blocks = (int)((agg_threads + 255) / 256);
    aggregate_kernel<<<agg_blocks, 256>>>(out, bg, nN);
}

// round 14
// speedup vs baseline: 1.4778x; 1.1835x over previous
#include <cuda_runtime.h>
#include <cuda_fp16.h>
#include <cstdint>
#include <cstddef>

#define N_NODES 100000
#define N_EDGES 1600000
#define IN_DIM  256
#define OUT_DIM 128

// ---------------- scratch (no cudaMalloc allowed) ----------------
__device__ __half g_h16[(size_t)N_NODES * OUT_DIM]; // h (unscaled, fp16)  (25.6 MB)
__device__ uint32_t g_wcf[16384];                   // Wc fp16 pairs, [ch][n][kloc]
__device__ float g_dinv[N_NODES];                   // 1/sqrt(deg)
__device__ int   g_cnt[N_NODES];                    // in-degree (edges only)
__device__ int   g_cur[N_NODES];                    // scatter cursors
__device__ int   g_rowptr[N_NODES + 1];             // CSR row pointers (by target)
__device__ int   g_srcs[N_EDGES];                   // sorted-by-target source ids
__device__ int   g_incl[N_NODES];                   // per-chunk inclusive scans
__device__ int   g_bsum[512];                       // block sums for scan
__device__ int   g_is64;                            // edge_index dtype flag

__device__ __forceinline__ uint32_t smem_u32(const void* p) {
    uint32_t a;
    asm("{ .reg .u64 t; cvta.to.shared.u64 t, %1; cvt.u32.u64 %0, t; }" : "=r"(a) : "l"(p));
    return a;
}

__device__ __forceinline__ uint32_t h2_bits(__half2 h) {
    return *reinterpret_cast<uint32_t*>(&h);
}

__device__ __forceinline__ void cp16(uint32_t dst, const void* src, bool pred) {
    int sz = pred ? 16 : 0;
    asm volatile("cp.async.ca.shared.global [%0], [%1], 16, %2;"
                 :: "r"(dst), "l"(src), "r"(sz) : "memory");
}

// ---------------- dtype detection (int64 vs int32 edge_index) ----------------
__global__ void detect_kernel(const void* __restrict__ ei) {
    if (threadIdx.x == 0 && blockIdx.x == 0) {
        const long long* p = (const long long*)ei;
        int is64 = 1;
        for (int i = 0; i < 8; i++) {
            long long v = p[i];
            if (v < 0 || v >= N_NODES) { is64 = 0; break; }
        }
        g_is64 = is64;
    }
}

__device__ __forceinline__ int load_idx(const void* __restrict__ ei, long long i, int is64) {
    if (is64) return (int)((const long long*)ei)[i];
    return ((const int*)ei)[i];
}

// ---------------- Wc = Wg @ Wp, converted to fp16 ----------------
// layout (half view): [ch][n][kloc]  ch = k>>5, kloc = k&31
__global__ void wc_kernel(const float* __restrict__ Wp, const float* __restrict__ Wg) {
    __shared__ float sWg[OUT_DIM];
    const int o2 = blockIdx.x;     // 0..127 (output row n)
    const int i  = threadIdx.x;    // 0..255 (k)
    if (i < OUT_DIM) sWg[i] = Wg[o2 * OUT_DIM + i];
    __syncthreads();
    float acc = 0.f;
#pragma unroll 8
    for (int o = 0; o < OUT_DIM; o++)
        acc += sWg[o] * Wp[o * IN_DIM + i];
    ((__half*)g_wcf)[(i >> 5) * 4096 + o2 * 32 + (i & 31)] = __float2half_rn(acc);
}

// ---------------- CSR build (round-10 scalar versions) ----------------
__global__ void zero_cnt_kernel(int nN) {
    int i = blockIdx.x * blockDim.x + threadIdx.x;
    if (i < nN) g_cnt[i] = 0;
}

__global__ void hist_kernel(const void* __restrict__ ei, int nE) {
    int e = blockIdx.x * blockDim.x + threadIdx.x;
    if (e >= nE) return;
    int c = load_idx(ei, (long long)nE + e, g_is64);   // col (target)
    atomicAdd(&g_cnt[c], 1);
}

__global__ void scanA_kernel(int nN) {
    __shared__ int s[256];
    int tid = threadIdx.x;
    int i = blockIdx.x * 256 + tid;
    int v = (i < nN) ? g_cnt[i] : 0;
    s[tid] = v;
    __syncthreads();
#pragma unroll
    for (int o = 1; o < 256; o <<= 1) {
        int t = (tid >= o) ? s[tid - o] : 0;
        __syncthreads();
        s[tid] += t;
        __syncthreads();
    }
    if (i < nN) g_incl[i] = s[tid];
    if (tid == 255) g_bsum[blockIdx.x] = s[255];
}

__global__ void scanB_kernel(int nb) {
    __shared__ int s[512];
    int tid = threadIdx.x;
    int v = (tid < nb) ? g_bsum[tid] : 0;
    s[tid] = v;
    __syncthreads();
#pragma unroll
    for (int o = 1; o < 512; o <<= 1) {
        int t = (tid >= o) ? s[tid - o] : 0;
        __syncthreads();
        s[tid] += t;
        __syncthreads();
    }
    if (tid < nb) g_bsum[tid] = s[tid] - v;   // exclusive
}

__global__ void scanC_kernel(int nN, int nE) {
    int i = blockIdx.x * blockDim.x + threadIdx.x;
    if (i >= nN) return;
    int incl = g_incl[i] + g_bsum[i >> 8];
    g_rowptr[i + 1] = incl;
    int cnt = g_cnt[i];
    g_cur[i] = incl - cnt;                    // exclusive offset
    g_dinv[i] = rsqrtf((float)(cnt + 1));     // +1 for self loop
    if (i == 0) g_rowptr[0] = 0;
}

__global__ void permute_kernel(const void* __restrict__ ei, int nE) {
    int e = blockIdx.x * blockDim.x + threadIdx.x;
    if (e >= nE) return;
    int is64 = g_is64;
    int r = load_idx(ei, e, is64);                     // row (source)
    int c = load_idx(ei, (long long)nE + e, is64);     // col (target)
    int p = atomicAdd(&g_cur[c], 1);
    g_srcs[p] = r;
}

// ---------------- GEMM: fp16 mma.sync + cp.async pipeline ----------------------
// CTA tile 128(M) x 128(N), K=256 in 8 chunks of 32. 8 warps = 4(M) x 2(N).
// A: cp.async raw fp32 double buffer (cvt to half2 at fragment load).
// B: cp.async pre-converted fp16 double buffer. MMA m16n8k16.f16.
#define KC 32
#define NCHUNK (IN_DIM / KC)
#define SROWA 36   // fp32 u32 per A smem row: 32 data + 4 pad (144B stride)
#define SROWB 20   // fp16-pair u32 per B smem row: 16 data + 4 pad (80B stride)
#define ABUF_U32 (128 * SROWA)          // 4608
#define BBUF_U32 (128 * SROWB)          // 2560
#define OFF_B0 (2 * ABUF_U32)           // 9216
#define GEMM_SMEM_BYTES ((2 * ABUF_U32 + 2 * BBUF_U32) * 4)  // 57344 B

__device__ __forceinline__ void mma_f16(float* c, const uint32_t* a, uint32_t b0, uint32_t b1) {
    asm volatile(
        "mma.sync.aligned.m16n8k16.row.col.f32.f16.f16.f32 "
        "{%0,%1,%2,%3}, {%4,%5,%6,%7}, {%8,%9}, {%0,%1,%2,%3};"
        : "+f"(c[0]), "+f"(c[1]), "+f"(c[2]), "+f"(c[3])
        : "r"(a[0]), "r"(a[1]), "r"(a[2]), "r"(a[3]), "r"(b0), "r"(b1));
}

__device__ __forceinline__ void stage_chunk(uint32_t sbase, int buf, const float* __restrict__ x,
                                            int m0, int ch, int tid, int nN) {
    const int kk = ch * KC;
#pragma unroll
    for (int i = 0; i < 4; i++) {
        int idx = tid + i * 256;
        int row = idx >> 3, q = idx & 7;
        int gm  = m0 + row;
        uint32_t dA = sbase + (uint32_t)(buf * ABUF_U32 + row * SROWA + q * 4) * 4u;
        cp16(dA, x + (size_t)gm * IN_DIM + kk + q * 4, gm < nN);
    }
    const uint4* bsrc = (const uint4*)(g_wcf + ch * 2048);
#pragma unroll
    for (int i = 0; i < 2; i++) {
        int idx = tid + i * 256;
        int n = idx >> 2, q = idx & 3;
        uint32_t dB = sbase + (uint32_t)(OFF_B0 + buf * BBUF_U32 + n * SROWB + q * 4) * 4u;
        cp16(dB, bsrc + idx, true);
    }
}

__global__ void __launch_bounds__(256) gemm_mma_kernel(const float* __restrict__ x, int nN) {
    extern __shared__ uint32_t smemD[];
    uint32_t sbase = smem_u32(smemD);

    const int tid  = threadIdx.x;
    const int wid  = tid >> 5;
    const int lane = tid & 31;
    const int g    = lane >> 2;   // groupID
    const int tg   = lane & 3;    // thread in group
    const int wm   = wid >> 1;    // 0..3  -> m offset 32*wm
    const int wn   = wid & 1;     // 0..1  -> n offset 64*wn
    const int m0   = blockIdx.x * 128;

    float acc[2][8][4];
#pragma unroll
    for (int mt = 0; mt < 2; mt++)
#pragma unroll
        for (int nt = 0; nt < 8; nt++)
#pragma unroll
            for (int j = 0; j < 4; j++) acc[mt][nt][j] = 0.f;

    stage_chunk(sbase, 0, x, m0, 0, tid, nN);
    asm volatile("cp.async.commit_group;" ::: "memory");

    for (int ch = 0; ch < NCHUNK; ch++) {
        const int buf = ch & 1;
        if (ch + 1 < NCHUNK) {
            stage_chunk(sbase, buf ^ 1, x, m0, ch + 1, tid, nN);
            asm volatile("cp.async.commit_group;" ::: "memory");
            asm volatile("cp.async.wait_group 1;" ::: "memory");
        } else {
            asm volatile("cp.async.wait_group 0;" ::: "memory");
        }
        __syncthreads();

        const float*    sa = (const float*)(smemD + buf * ABUF_U32);
        const uint32_t* sb = smemD + OFF_B0 + buf * BBUF_U32;

#pragma unroll
        for (int ks = 0; ks < KC / 16; ks++) {
            const int kb = ks * 16;
            uint32_t a[2][4];
#pragma unroll
            for (int mt = 0; mt < 2; mt++) {
                int r0 = (wm * 32 + mt * 16 + g) * SROWA + kb + tg * 2;
                int r1 = (wm * 32 + mt * 16 + g + 8) * SROWA + kb + tg * 2;
                float2 f0 = *(const float2*)(sa + r0);
                float2 f1 = *(const float2*)(sa + r1);
                float2 f2 = *(const float2*)(sa + r0 + 8);
                float2 f3 = *(const float2*)(sa + r1 + 8);
                a[mt][0] = h2_bits(__floats2half2_rn(f0.x, f0.y));
                a[mt][1] = h2_bits(__floats2half2_rn(f1.x, f1.y));
                a[mt][2] = h2_bits(__floats2half2_rn(f2.x, f2.y));
                a[mt][3] = h2_bits(__floats2half2_rn(f3.x, f3.y));
            }
#pragma unroll
            for (int nt = 0; nt < 8; nt++) {
                int n = wn * 64 + nt * 8 + g;
                int o = n * SROWB + ks * 8 + tg;
                uint32_t b0 = sb[o], b1 = sb[o + 4];
#pragma unroll
                for (int mt = 0; mt < 2; mt++)
                    mma_f16(acc[mt][nt], a[mt], b0, b1);
            }
        }
        __syncthreads();
    }

    // epilogue: store h (unscaled) as fp16
#pragma unroll
    for (int mt = 0; mt < 2; mt++) {
        int r0 = m0 + wm * 32 + mt * 16 + g;
        int r1 = r0 + 8;
#pragma unroll
        for (int nt = 0; nt < 8; nt++) {
            int col = wn * 64 + nt * 8 + tg * 2;
            if (r0 < nN) {
                __half2 o = __floats2half2_rn(acc[mt][nt][0], acc[mt][nt][1]);
                *(__half2*)(g_h16 + (size_t)r0 * OUT_DIM + col) = o;
            }
            if (r1 < nN) {
                __half2 o = __floats2half2_rn(acc[mt][nt][2], acc[mt][nt][3]);
                *(__half2*)(g_h16 + (size_t)r1 * OUT_DIM + col) = o;
            }
        }
    }
}

// ---------------- fused aggregate + finalize (paired-edge half-warp gather) ------
__device__ __forceinline__ void accu4(float* a, uint4 raw, float d) {
    __half2* h = (__half2*)&raw;
#pragma unroll
    for (int k = 0; k < 4; k++) {
        float2 f = __half22float2(h[k]);
        a[2 * k]     += f.x * d;
        a[2 * k + 1] += f.y * d;
    }
}

__global__ void __launch_bounds__(256) aggregate_kernel(
    float* __restrict__ out, const float* __restrict__ bg, int nN) {
    int w    = (int)((blockIdx.x * (unsigned)blockDim.x + threadIdx.x) >> 5);
    int lane = threadIdx.x & 31;
    int hl   = lane >> 4;          // half id: item parity
    int sl   = lane & 15;          // sublane: feature group 8*sl..8*sl+7
    if (w >= nN) return;

    int beg = g_rowptr[w];
    int end = g_rowptr[w + 1];
    int nItems = 1 + (end - beg);  // self + edges
    float dw = g_dinv[w];

    float a[8] = {0.f, 0.f, 0.f, 0.f, 0.f, 0.f, 0.f, 0.f};

    int j = hl;
    for (; j + 10 < nItems; j += 12) {
        int rows[6];
#pragma unroll
        for (int t = 0; t < 6; t++) {
            int jj = j + 2 * t;
            rows[t] = (jj == 0) ? w : __ldg(&g_srcs[beg + jj - 1]);
        }
        uint4 rr[6];
#pragma unroll
        for (int t = 0; t < 6; t++)
            rr[t] = __ldg((const uint4*)(g_h16 + (size_t)rows[t] * OUT_DIM) + sl);
        float dd[6];
#pragma unroll
        for (int t = 0; t < 6; t++) dd[t] = __ldg(&g_dinv[rows[t]]);
#pragma unroll
        for (int t = 0; t < 6; t++) accu4(a, rr[t], dd[t]);
    }
    for (; j < nItems; j += 2) {
        int row = (j == 0) ? w : __ldg(&g_srcs[beg + j - 1]);
        uint4 r = __ldg((const uint4*)(g_h16 + (size_t)row * OUT_DIM) + sl);
        float d = __ldg(&g_dinv[row]);
        accu4(a, r, d);
    }

#pragma unroll
    for (int k = 0; k < 8; k++) a[k] += __shfl_xor_sync(0xffffffffu, a[k], 16);

    float4 b0 = ((const float4*)bg)[sl * 2];
    float4 b1 = ((const float4*)bg)[sl * 2 + 1];
    a[0] = a[0] * dw + b0.x;  a[1] = a[1] * dw + b0.y;
    a[2] = a[2] * dw + b0.z;  a[3] = a[3] * dw + b0.w;
    a[4] = a[4] * dw + b1.x;  a[5] = a[5] * dw + b1.y;
    a[6] = a[6] * dw + b1.z;  a[7] = a[7] * dw + b1.w;

    float ss = 0.f;
#pragma unroll
    for (int k = 0; k < 8; k++) ss += a[k] * a[k];
#pragma unroll
    for (int o = 8; o > 0; o >>= 1) ss += __shfl_xor_sync(0xffffffffu, ss, o);
    float inv = 1.0f / fmaxf(sqrtf(ss), 1e-12f);

    float4 v = (hl == 0)
        ? make_float4(a[0] * inv, a[1] * inv, a[2] * inv, a[3] * inv)
        : make_float4(a[4] * inv, a[5] * inv, a[6] * inv, a[7] * inv);
    *(float4*)(out + (size_t)w * OUT_DIM + sl * 8 + hl * 4) = v;
}

// ---------------- launch (stream fork/join, capture-legal, round-10 order) -------
extern "C" void kernel_launch(void* const* d_in, const int* in_sizes, int n_in,
                              void* d_out, int out_size) {
    const float* x  = (const float*)d_in[0];
    const void*  ei = d_in[1];
    const float* Wp = (const float*)d_in[2];
    const float* Wg = (const float*)d_in[3];
    const float* bg = (const float*)d_in[4];
    float* out = (float*)d_out;

    const int nN = in_sizes[0] / IN_DIM;   // 100000
    const int nE = in_sizes[1] / 2;        // 1600000
    const int nScanBlocks = (nN + 255) / 256;

    static cudaStream_t s2;
    static cudaEvent_t evF, evJ;
    static bool inited = false;
    if (!inited) {
        cudaStreamCreateWithFlags(&s2, cudaStreamNonBlocking);
        cudaEventCreateWithFlags(&evF, cudaEventDisableTiming);
        cudaEventCreateWithFlags(&evJ, cudaEventDisableTiming);
        cudaFuncSetAttribute(gemm_mma_kernel,
                             cudaFuncAttributeMaxDynamicSharedMemorySize,
                             GEMM_SMEM_BYTES);
        inited = true;
    }

    // fork: CSR chain on s2, GEMM chain on default stream
    cudaEventRecord(evF, 0);
    cudaStreamWaitEvent(s2, evF, 0);

    detect_kernel<<<1, 32, 0, s2>>>(ei);
    zero_cnt_kernel<<<(nN + 255) / 256, 256, 0, s2>>>(nN);
    hist_kernel<<<(nE + 255) / 256, 256, 0, s2>>>(ei, nE);
    scanA_kernel<<<nScanBlocks, 256, 0, s2>>>(nN);
    scanB_kernel<<<1, 512, 0, s2>>>(nScanBlocks);
    scanC_kernel<<<(nN + 255) / 256, 256, 0, s2>>>(nN, nE);
    permute_kernel<<<(nE + 255) / 256, 256, 0, s2>>>(ei, nE);
    cudaEventRecord(evJ, s2);

    wc_kernel<<<OUT_DIM, 256>>>(Wp, Wg);
    gemm_mma_kernel<<<(nN + 127) / 128, 256, GEMM_SMEM_BYTES>>>(x, nN);

    // join
    cudaStreamWaitEvent(0, evJ, 0);

    long long agg_threads = (long long)nN * 32;
    int agg_blocks = (int)((agg_threads + 255) / 256);
    aggregate_kernel<<<agg_blocks, 256>>>(out, bg, nN);
}